// round 13
// baseline (speedup 1.0000x reference)
#include <cuda_runtime.h>

#define NN 16384
#define MN 8192
#define MM 4096
#define Kn 31
#define PC 8
#define PT 512

__device__ float dF2[NN],dF3[NN],dF4[NN],dF5[NN],dF6[NN];
__device__ float dF1T[NN],dF2T[NN],dF3T[NN],dF4T[NN],dF5T[NN],dF6T[NN];
__device__ float dHT[MN];
__device__ float dA[6*NN],dB[6*NN];
__device__ float dQ2[NN],dQ3[NN],dQ4[NN],dQ5[NN];
__device__ float dPp[(Kn+1)*NN];
__device__ float dU[Kn*MN],dPy[Kn*MM],dG[Kn*MN];
__device__ float dZ[Kn*MN];
__device__ float dPt[128*NN];

// ---- cluster-wide barrier (grid == one 8-CTA cluster) ----
__device__ __forceinline__ void csync() {
  __threadfence();
  asm volatile("barrier.cluster.arrive.aligned;" ::: "memory");
  asm volatile("barrier.cluster.wait.aligned;" ::: "memory");
}

// ---- warp-per-row GEMM, batched loads (MLP=16): O = C + sgn*(A@B) ----
__device__ __forceinline__ void prow(const float* A, const float* B, const float* C,
                                     float* O, int r, int cols, int kd, float sgn) {
  int lane = threadIdx.x & 31, nc4 = cols >> 2;
  if (lane >= nc4) return;
  const float4* B4 = (const float4*)B;
  const float* Ar = A + (size_t)r * kd;
  float4 acc = make_float4(0.f, 0.f, 0.f, 0.f);
  for (int kb = 0; kb < kd; kb += 16) {
    float4 bt[16]; float at[16];
#pragma unroll
    for (int j = 0; j < 16; j++) {
      bt[j] = B4[(size_t)(kb + j) * nc4 + lane];
      at[j] = Ar[kb + j];
    }
#pragma unroll
    for (int j = 0; j < 16; j++) {
      acc.x = fmaf(at[j], bt[j].x, acc.x); acc.y = fmaf(at[j], bt[j].y, acc.y);
      acc.z = fmaf(at[j], bt[j].z, acc.z); acc.w = fmaf(at[j], bt[j].w, acc.w);
    }
  }
  float4 o = make_float4(sgn * acc.x, sgn * acc.y, sgn * acc.z, sgn * acc.w);
  if (C) { float4 c4 = ((const float4*)C)[(size_t)r * nc4 + lane];
           o.x += c4.x; o.y += c4.y; o.z += c4.z; o.w += c4.w; }
  ((float4*)O)[(size_t)r * nc4 + lane] = o;
}

__device__ __forceinline__ void trow(const float* S, float* D, int r, int dcols, int ss) {
  int lane = threadIdx.x & 31, nc4 = dcols >> 2;
  if (lane >= nc4) return;
  float4 v;
  v.x = S[(size_t)(4*lane+0)*ss + r]; v.y = S[(size_t)(4*lane+1)*ss + r];
  v.z = S[(size_t)(4*lane+2)*ss + r]; v.w = S[(size_t)(4*lane+3)*ss + r];
  ((float4*)D)[(size_t)r * nc4 + lane] = v;
}

// ---- GJ pivot loop: 64x192 augmented, 512 thr = 64 rows x 8 chunks of 24 ----
__device__ __forceinline__ void gjcore(float (&a)[24], float* piv, float* fc) {
  int r = threadIdx.x & 63, ch = threadIdx.x >> 6, c0 = ch * 24;
#pragma unroll 1
  for (int p = 0; p < 64; p++) {
    int pc = p / 24, pi = p - pc * 24;
    if (ch == pc) fc[r] = a[pi];
    __syncthreads();
    float f = fc[r];
    if (r == p) {
      float inv = 1.0f / fc[p];
#pragma unroll
      for (int j = 0; j < 24; j++) { a[j] *= inv; piv[c0 + j] = a[j]; }
    }
    __syncthreads();
    if (r != p) {
#pragma unroll
      for (int j = 0; j < 24; j++) a[j] = fmaf(-f, piv[c0 + j], a[j]);
    }
  }
}

// shared layout (floats): [0,8192) sYv (also sw1/sw2 during stage A)
// [8192,10240) sS  [10240,11264) sG  [11264,11456) piv  [11456,11520) fc
#define SMEMF 11520

// ---- persistent serial-chain kernel: one 8-CTA cluster ----
__global__ void __launch_bounds__(PT, 1) __cluster_dims__(PC, 1, 1)
kchain(const float* F, const float* H, const float* Q,
       const float* R, const float* P0) {
  extern __shared__ float sm[];
  float* sYv = sm;
  float* sw1 = sm;                // stage-A scratch, overlaps sYv
  float* sw2 = sm + 2112;
  float* sS  = sm + 8192;
  float* sG  = sm + 10240;
  float* piv = sm + 11264;
  float* fc  = sm + 11456;
  int wid = threadIdx.x >> 5, lane = threadIdx.x & 31;
  int gw = blockIdx.x * 16 + wid;
  const int NW = PC * 16;
  // S0
  for (int w = gw; w < 640; w += NW) {
    if (w < 128) prow(F, F, 0, dF2, w, 128, 128, 1.f);
    else if (w < 256) prow(F, P0, 0, dA, w-128, 128, 128, 1.f);
    else if (w < 384) prow(F, Q, 0, dA+NN, w-256, 128, 128, 1.f);
    else if (w < 512) trow(F, dF1T, w-384, 128, 128);
    else trow(H, dHT, w-512, 64, 128);
  }
  csync();
  // S1
  for (int w = gw; w < 768; w += NW) {
    if (w < 128) prow(F, dF2, 0, dF3, w, 128, 128, 1.f);
    else if (w < 256) prow(dF2, dF2, 0, dF4, w-128, 128, 128, 1.f);
    else if (w < 384) trow(dF2, dF2T, w-256, 128, 128);
    else if (w < 512) prow(dA+NN, dF1T, 0, dB+NN, w-384, 128, 128, 1.f);
    else if (w < 640) prow(dF2, Q, 0, dA+2*NN, w-512, 128, 128, 1.f);
    else prow(dA, dF1T, Q, dPp, w-640, 128, 128, 1.f);
  }
  csync();
  // S2
  for (int w = gw; w < 896; w += NW) {
    if (w < 128) prow(dF2, dF3, 0, dF5, w, 128, 128, 1.f);
    else if (w < 256) prow(dF3, dF3, 0, dF6, w-128, 128, 128, 1.f);
    else if (w < 384) trow(dF3, dF3T, w-256, 128, 128);
    else if (w < 512) trow(dF4, dF4T, w-384, 128, 128);
    else if (w < 640) prow(dA+2*NN, dF2T, 0, dB+2*NN, w-512, 128, 128, 1.f);
    else if (w < 768) prow(dF3, Q, 0, dA+3*NN, w-640, 128, 128, 1.f);
    else prow(dF4, Q, 0, dA+4*NN, w-768, 128, 128, 1.f);
  }
  csync();
  // S3
  for (int w = gw; w < 640; w += NW) {
    if (w < 128) trow(dF5, dF5T, w, 128, 128);
    else if (w < 256) trow(dF6, dF6T, w-128, 128, 128);
    else if (w < 384) prow(dA+3*NN, dF3T, 0, dB+3*NN, w-256, 128, 128, 1.f);
    else if (w < 512) prow(dA+4*NN, dF4T, 0, dB+4*NN, w-384, 128, 128, 1.f);
    else prow(dF5, Q, 0, dA+5*NN, w-512, 128, 128, 1.f);
  }
  csync();
  // S4
  for (int w = gw; w < 640; w += NW) {
    if (w < 128) prow(dA+5*NN, dF5T, 0, dB+5*NN, w, 128, 128, 1.f);
    else {
      int i = (w - 128) * 32 + lane;
      float q  = Q[i];
      float q2 = q  + dB[1*NN+i]; dQ2[i] = q2;
      float q3 = q2 + dB[2*NN+i]; dQ3[i] = q3;
      float q4 = q3 + dB[3*NN+i]; dQ4[i] = q4;
      float q5 = q4 + dB[4*NN+i]; dQ5[i] = q5;
    }
  }
  csync();
  // ---- 31 observation cycles ----
  for (int c = 0; c < Kn; c++) {
    const float4* Pc4 = (const float4*)(dPp + (size_t)c * NN);
    // stage A: fused dual-row GEMM sharing Pp loads
    {
      int grow = blockIdx.x * 16 + wid;        // G/S row 0..127
      bool dual = (wid < 8);
      int urow = blockIdx.x * 8 + wid;         // U/Py row 0..63
      const float* Ar1 = dF3 + (size_t)grow * 128;
      const float* Ar2 = dual ? (H + (size_t)urow * 128) : Ar1;
      float4 w1 = make_float4(0.f,0.f,0.f,0.f);
      float4 w2 = make_float4(0.f,0.f,0.f,0.f);
      for (int kb = 0; kb < 128; kb += 8) {
        float4 bt[8]; float a1[8]; float a2[8];
#pragma unroll
        for (int j = 0; j < 8; j++) {
          bt[j] = Pc4[(kb+j)*32 + lane];
          a1[j] = Ar1[kb+j];
          a2[j] = Ar2[kb+j];
        }
#pragma unroll
        for (int j = 0; j < 8; j++) {
          w1.x = fmaf(a1[j], bt[j].x, w1.x); w1.y = fmaf(a1[j], bt[j].y, w1.y);
          w1.z = fmaf(a1[j], bt[j].z, w1.z); w1.w = fmaf(a1[j], bt[j].w, w1.w);
          w2.x = fmaf(a2[j], bt[j].x, w2.x); w2.y = fmaf(a2[j], bt[j].y, w2.y);
          w2.z = fmaf(a2[j], bt[j].z, w2.z); w2.w = fmaf(a2[j], bt[j].w, w2.w);
        }
      }
      ((float4*)(sw1 + wid*132))[lane] = w1;
      if (dual) ((float4*)(sw2 + wid*132))[lane] = w2;
      __syncwarp();
      // G,S for grow (S,G kept in shared; G also to global for GJ)
      {
        const float* swr = sw1 + wid*132;
        float g0 = 0.f, g1 = 0.f;
        float4 s = make_float4(0.f, 0.f, 0.f, 0.f);
        const float4* F3T4 = (const float4*)dF3T;
        const float2* HT2 = (const float2*)dHT;
        for (int kb = 0; kb < 128; kb += 8) {
          float4 ft[8]; float2 ht[8];
#pragma unroll
          for (int j = 0; j < 8; j++) { ft[j] = F3T4[(kb+j)*32 + lane]; ht[j] = HT2[(kb+j)*32 + lane]; }
#pragma unroll
          for (int j = 0; j < 8; j++) {
            float wk = swr[kb+j];
            g0 = fmaf(wk, ht[j].x, g0); g1 = fmaf(wk, ht[j].y, g1);
            s.x = fmaf(wk, ft[j].x, s.x); s.y = fmaf(wk, ft[j].y, s.y);
            s.z = fmaf(wk, ft[j].z, s.z); s.w = fmaf(wk, ft[j].w, s.w);
          }
        }
        float4 q = ((const float4*)(dQ3 + (size_t)grow * 128))[lane];
        s.x += q.x; s.y += q.y; s.z += q.z; s.w += q.w;
        ((float4*)(sS + wid*128))[lane] = s;
        sG[wid*64 + 2*lane] = g0; sG[wid*64 + 2*lane + 1] = g1;
        ((float2*)(dG + (size_t)c*MN + (size_t)grow*64))[lane] = make_float2(g0, g1);
      }
      // U,Py for urow
      if (dual) {
        const float* swr = sw2 + wid*132;
        ((float4*)(dU + (size_t)c*MN + (size_t)urow*128))[lane] = w2;
        float p0 = 0.f, p1 = 0.f;
        const float2* HT2 = (const float2*)dHT;
        for (int kb = 0; kb < 128; kb += 8) {
          float2 ht[8];
#pragma unroll
          for (int j = 0; j < 8; j++) ht[j] = HT2[(kb+j)*32 + lane];
#pragma unroll
          for (int j = 0; j < 8; j++) {
            float wk = swr[kb+j];
            p0 = fmaf(wk, ht[j].x, p0); p1 = fmaf(wk, ht[j].y, p1);
          }
        }
        p0 += R[urow*64 + 2*lane]; p1 += R[urow*64 + 2*lane + 1];
        ((float2*)(dPy + (size_t)c*MM + (size_t)urow*64))[lane] = make_float2(p0, p1);
      }
    }
    csync();
    // GJ redundantly per CTA: sYv = Py^-1 @ G^T (overwrites sw scratch)
    {
      int r = threadIdx.x & 63, ch = threadIdx.x >> 6, c0 = ch * 24;
      const float* Pyc = dPy + (size_t)c * MM;
      const float* Gc  = dG + (size_t)c * MN;
      float a[24];
#pragma unroll
      for (int j = 0; j < 24; j++) {
        int col = c0 + j;
        a[j] = (col < 64) ? Pyc[r*64 + col] : Gc[(size_t)(col-64)*64 + r];
      }
      gjcore(a, piv, fc);
#pragma unroll
      for (int j = 0; j < 24; j++) {
        int col = c0 + j;
        if (col >= 64) sYv[r*128 + (col-64)] = a[j];
      }
      __syncthreads();
    }
    // Pp' = sS - sG @ sYv  (16 rows/CTA, one per warp, all shared)
    {
      int row = blockIdx.x * 16 + wid;
      float4 acc = ((const float4*)(sS + wid*128))[lane];
      for (int ab = 0; ab < 64; ab += 8) {
        float gt[8];
#pragma unroll
        for (int j = 0; j < 8; j++) gt[j] = sG[wid*64 + ab + j];
#pragma unroll
        for (int j = 0; j < 8; j++) {
          float4 yv = ((const float4*)(sYv + (ab+j)*128))[lane];
          acc.x = fmaf(-gt[j], yv.x, acc.x); acc.y = fmaf(-gt[j], yv.y, acc.y);
          acc.z = fmaf(-gt[j], yv.z, acc.z); acc.w = fmaf(-gt[j], yv.w, acc.w);
        }
      }
      ((float4*)(dPp + (size_t)(c+1)*NN + (size_t)row*128))[lane] = acc;
    }
    csync();
  }
}

// ---- post kernels ----
__global__ void __launch_bounds__(512, 1) kgjpost() {   // Z_c = Py_c^-1 @ U_c
  __shared__ float piv[192]; __shared__ float fc[64];
  int c = blockIdx.x;
  int r = threadIdx.x & 63, ch = threadIdx.x >> 6, c0 = ch * 24;
  float a[24];
#pragma unroll
  for (int j = 0; j < 24; j++) {
    int col = c0 + j;
    a[j] = (col < 64) ? dPy[(size_t)c*MM + r*64 + col]
                      : dU[(size_t)c*MN + r*128 + (col-64)];
  }
  gjcore(a, piv, fc);
#pragma unroll
  for (int j = 0; j < 24; j++) {
    int col = c0 + j;
    if (col >= 64) dZ[(size_t)c*MN + r*128 + (col-64)] = a[j];
  }
}
__global__ void __launch_bounds__(256, 1) kPu() {       // Pu = Pp - U^T @ Z
  int c = blockIdx.y, w = blockIdx.x * 8 + (threadIdx.x >> 5), lane = threadIdx.x & 31;
  const float* U = dU + (size_t)c*MN;
  const float4* Z4 = (const float4*)(dZ + (size_t)c*MN);
  float4 acc = ((const float4*)(dPp + (size_t)c*NN))[w*32 + lane];
  for (int ab = 0; ab < 64; ab += 8) {
    float gt[8]; float4 zt[8];
#pragma unroll
    for (int j = 0; j < 8; j++) { gt[j] = U[(ab+j)*128 + w]; zt[j] = Z4[(ab+j)*32 + lane]; }
#pragma unroll
    for (int j = 0; j < 8; j++) {
      acc.x = fmaf(-gt[j], zt[j].x, acc.x); acc.y = fmaf(-gt[j], zt[j].y, acc.y);
      acc.z = fmaf(-gt[j], zt[j].z, acc.z); acc.w = fmaf(-gt[j], zt[j].w, acc.w);
    }
  }
  ((float4*)(dPt + (size_t)(4*c)*NN))[w*32 + lane] = acc;
}
// fused: P[4c+2] = F Pu F1T + Q ; P[4c+3] = F2 Pu F2T + Q2
__global__ void __launch_bounds__(256, 1) kPmid(const float* F, const float* Q) {
  __shared__ float sw[8][132];
  int wid = threadIdx.x >> 5, lane = threadIdx.x & 31;
  int c = blockIdx.y;
  int tk = blockIdx.x * 8 + wid;
  int jj = tk >> 7, row = tk & 127;
  const float* A  = jj ? dF2 : F;
  const float4* Bt4 = (const float4*)(jj ? dF2T : dF1T);
  const float4* Qj4 = (const float4*)((jj ? dQ2 : Q) + (size_t)row*128);
  const float4* Pu4 = (const float4*)(dPt + (size_t)(4*c)*NN);
  const float* Ar = A + (size_t)row*128;
  float4 w = make_float4(0.f,0.f,0.f,0.f);
  for (int kb = 0; kb < 128; kb += 8) {
    float4 bt[8]; float at[8];
#pragma unroll
    for (int j = 0; j < 8; j++) { bt[j] = Pu4[(kb+j)*32 + lane]; at[j] = Ar[kb+j]; }
#pragma unroll
    for (int j = 0; j < 8; j++) {
      w.x = fmaf(at[j], bt[j].x, w.x); w.y = fmaf(at[j], bt[j].y, w.y);
      w.z = fmaf(at[j], bt[j].z, w.z); w.w = fmaf(at[j], bt[j].w, w.w);
    }
  }
  ((float4*)(sw[wid]))[lane] = w;
  __syncwarp();
  const float* swr = sw[wid];
  float4 o = Qj4[lane];
  for (int kb = 0; kb < 128; kb += 8) {
    float4 ft[8];
#pragma unroll
    for (int j = 0; j < 8; j++) ft[j] = Bt4[(kb+j)*32 + lane];
#pragma unroll
    for (int j = 0; j < 8; j++) {
      float wk = swr[kb+j];
      o.x = fmaf(wk, ft[j].x, o.x); o.y = fmaf(wk, ft[j].y, o.y);
      o.z = fmaf(wk, ft[j].z, o.z); o.w = fmaf(wk, ft[j].w, o.w);
    }
  }
  ((float4*)(dPt + (size_t)(4*c + 2 + jj)*NN + (size_t)row*128))[lane] = o;
}
// fused tail: P[125+k] = F^{4+k} Pu30 F^{4+k}T + Q_{4+k}
__global__ void __launch_bounds__(256, 1) kPtail(const float* Q) {
  __shared__ float sw[8][132];
  int wid = threadIdx.x >> 5, lane = threadIdx.x & 31;
  int k = blockIdx.y;
  int row = blockIdx.x * 8 + wid;
  const float* A  = (k == 0) ? dF4 : (k == 1) ? dF5 : dF6;
  const float4* Bt4 = (const float4*)((k == 0) ? dF4T : (k == 1) ? dF5T : dF6T);
  const float4* Qk4 = (const float4*)(((k == 0) ? dQ4 : dQ5) + (size_t)row*128);
  const float4* Pu4 = (const float4*)(dPt + (size_t)120*NN);
  const float* Ar = A + (size_t)row*128;
  float4 w = make_float4(0.f,0.f,0.f,0.f);
  for (int kb = 0; kb < 128; kb += 8) {
    float4 bt[8]; float at[8];
#pragma unroll
    for (int j = 0; j < 8; j++) { bt[j] = Pu4[(kb+j)*32 + lane]; at[j] = Ar[kb+j]; }
#pragma unroll
    for (int j = 0; j < 8; j++) {
      w.x = fmaf(at[j], bt[j].x, w.x); w.y = fmaf(at[j], bt[j].y, w.y);
      w.z = fmaf(at[j], bt[j].z, w.z); w.w = fmaf(at[j], bt[j].w, w.w);
    }
  }
  ((float4*)(sw[wid]))[lane] = w;
  __syncwarp();
  const float* swr = sw[wid];
  float4 o = Qk4[lane];
  if (k == 2) {
    float4 b5 = ((const float4*)(dB + 5*NN + (size_t)row*128))[lane];
    o.x += b5.x; o.y += b5.y; o.z += b5.z; o.w += b5.w;
  }
  for (int kb = 0; kb < 128; kb += 8) {
    float4 ft[8];
#pragma unroll
    for (int j = 0; j < 8; j++) ft[j] = Bt4[(kb+j)*32 + lane];
#pragma unroll
    for (int j = 0; j < 8; j++) {
      float wk = swr[kb+j];
      o.x = fmaf(wk, ft[j].x, o.x); o.y = fmaf(wk, ft[j].y, o.y);
      o.z = fmaf(wk, ft[j].z, o.z); o.w = fmaf(wk, ft[j].w, o.w);
    }
  }
  ((float4*)(dPt + (size_t)(125 + k)*NN + (size_t)row*128))[lane] = o;
}
__global__ void __launch_bounds__(256, 1) kcopy() {
  int i = blockIdx.x * 256 + threadIdx.x;
  ((float4*)(dPt + (size_t)124*NN))[i] = ((const float4*)(dPp + (size_t)Kn*NN))[i];
}

// ---- per-batch state trajectory: F row in registers, HT in smem ----
__global__ void __launch_bounds__(128, 1) xphase(const float* __restrict__ x0,
                                                 const float* __restrict__ y,
                                                 const float* __restrict__ Fg,
                                                 float* __restrict__ xs) {
  __shared__ float sx[128], sxp[128], sres[64];
  __shared__ float sHT[128*65];
  int b = blockIdx.x, i = threadIdx.x;
  float fr[128];
#pragma unroll
  for (int j = 0; j < 128; j++) fr[j] = Fg[i*128 + j];
  for (int idx = i; idx < 128*64; idx += 128) {
    int j = idx >> 6, a = idx & 63;
    sHT[j*65 + a] = dHT[idx];
  }
  sx[i] = x0[b*128 + i];
  __syncthreads();
#pragma unroll 1
  for (int t = 0; t < 128; t++) {
    bool isobs = ((t & 3) == 0) && (t <= 120);
    bool copys = (t >= 1) && (((t-1) & 3) == 0) && ((t-1) <= 120);
    float xp;
    if (!copys) {
      float a0 = 0.f, a1 = 0.f;
#pragma unroll
      for (int j = 0; j < 128; j += 2) {
        a0 = fmaf(fr[j], sx[j], a0);
        a1 = fmaf(fr[j+1], sx[j+1], a1);
      }
      xp = a0 + a1;
    } else xp = sx[i];
    __syncthreads();
    sxp[i] = xp;
    __syncthreads();
    float xn = xp;
    if (isobs) {
      int c = t >> 2;
      if (i < 64) {
        float acc = 0.f;
#pragma unroll
        for (int j = 0; j < 128; j++) acc = fmaf(sHT[j*65 + i], sxp[j], acc);
        sres[i] = y[((size_t)b*Kn + c)*64 + i] - acc;
      }
      __syncthreads();
      const float* Zc = dZ + (size_t)c*MN;
      float acc = 0.f;
      for (int ab = 0; ab < 64; ab += 8) {
        float zt[8];
#pragma unroll
        for (int j = 0; j < 8; j++) zt[j] = Zc[(ab+j)*128 + i];
#pragma unroll
        for (int j = 0; j < 8; j++) acc = fmaf(zt[j], sres[ab+j], acc);
      }
      xn = xp + acc;
    }
    xs[((size_t)b*128 + t)*128 + i] = xn;
    __syncthreads();
    sx[i] = xn;
    __syncthreads();
  }
}
__global__ void __launch_bounds__(256, 1) kbcast(float4* __restrict__ Ps) {
  int idx = blockIdx.x * blockDim.x + threadIdx.x;
  int b = blockIdx.y;
  int t = idx >> 12;
  int ts = (((t & 3) == 1) && (t < 122)) ? (t - 1) : t;
  Ps[(size_t)b * 524288 + idx] = ((const float4*)dPt)[(size_t)ts * 4096 + (idx & 4095)];
}

extern "C" void kernel_launch(void* const* d_in, const int* in_sizes, int n_in,
                              void* d_out, int out_size) {
  (void)in_sizes; (void)n_in; (void)out_size;
  const float* y  = (const float*)d_in[1];
  const float* x0 = (const float*)d_in[2];
  const float* P0 = (const float*)d_in[3];
  const float* F  = (const float*)d_in[5];
  const float* H  = (const float*)d_in[6];
  const float* Q  = (const float*)d_in[7];
  const float* R  = (const float*)d_in[8];
  float* xs = (float*)d_out;
  float* Ps = (float*)d_out + (size_t)32 * 128 * 128;

  const int smemB = SMEMF * 4;
  cudaFuncSetAttribute(kchain, cudaFuncAttributeMaxDynamicSharedMemorySize, smemB);
  kchain<<<PC, PT, smemB>>>(F, H, Q, R, P0);
  kgjpost<<<Kn, 512>>>();
  kPu<<<dim3(16, Kn), 256>>>();
  kPmid<<<dim3(32, Kn), 256>>>(F, Q);
  kPtail<<<dim3(16, 3), 256>>>(Q);
  kcopy<<<16, 256>>>();
  xphase<<<32, 128>>>(x0, y, F, xs);
  kbcast<<<dim3(2048, 32), 256>>>((float4*)Ps);
}

// round 15
// speedup vs baseline: 1.2359x; 1.2359x over previous
#include <cuda_runtime.h>

#define NN 16384
#define MN 8192
#define MM 4096
#define Kn 31
#define PC 32
#define PT 512

__device__ float dF2[NN],dF3[NN],dF4[NN],dF5[NN],dF6[NN];
__device__ float dF1T[NN],dF2T[NN],dF3T[NN],dF4T[NN],dF5T[NN],dF6T[NN];
__device__ float dHT[MN];
__device__ float dA[6*NN],dB[6*NN];
__device__ float dQ2[NN],dQ3[NN],dQ4[NN],dQ5[NN];
__device__ float dPp[(Kn+1)*NN];
__device__ float dU[Kn*MN],dPy[Kn*MM],dG[Kn*MN],dS[Kn*NN];
__device__ float dZ[Kn*MN];
__device__ float dPt[128*NN];
__device__ unsigned dFlags[PC*32];   // one 128B line per CTA; monotonic across replays

// ---- grid-wide barrier: per-CTA flag lines, no atomics ----
__device__ __forceinline__ void gbar(unsigned gen) {
  __syncthreads();
  if (threadIdx.x == 0) {
    __threadfence();
    dFlags[blockIdx.x * 32] = gen;
  }
  if (threadIdx.x < PC) {
    while (((volatile unsigned*)dFlags)[threadIdx.x * 32] < gen) { }
  }
  __threadfence();
  __syncthreads();
}

// ---- warp-per-row GEMM, batched loads (MLP=8): O = C + sgn*(A@B) ----
__device__ __forceinline__ void prow(const float* A, const float* B, const float* C,
                                     float* O, int r, int cols, int kd, float sgn) {
  int lane = threadIdx.x & 31, nc4 = cols >> 2;
  if (lane >= nc4) return;
  const float4* B4 = (const float4*)B;
  const float* Ar = A + (size_t)r * kd;
  float4 acc = make_float4(0.f, 0.f, 0.f, 0.f);
  for (int kb = 0; kb < kd; kb += 8) {
    float4 bt[8]; float at[8];
#pragma unroll
    for (int j = 0; j < 8; j++) {
      bt[j] = B4[(size_t)(kb + j) * nc4 + lane];
      at[j] = Ar[kb + j];
    }
#pragma unroll
    for (int j = 0; j < 8; j++) {
      acc.x = fmaf(at[j], bt[j].x, acc.x); acc.y = fmaf(at[j], bt[j].y, acc.y);
      acc.z = fmaf(at[j], bt[j].z, acc.z); acc.w = fmaf(at[j], bt[j].w, acc.w);
    }
  }
  float4 o = make_float4(sgn * acc.x, sgn * acc.y, sgn * acc.z, sgn * acc.w);
  if (C) { float4 c4 = ((const float4*)C)[(size_t)r * nc4 + lane];
           o.x += c4.x; o.y += c4.y; o.z += c4.z; o.w += c4.w; }
  ((float4*)O)[(size_t)r * nc4 + lane] = o;
}

__device__ __forceinline__ void trow(const float* S, float* D, int r, int dcols, int ss) {
  int lane = threadIdx.x & 31, nc4 = dcols >> 2;
  if (lane >= nc4) return;
  float4 v;
  v.x = S[(size_t)(4*lane+0)*ss + r]; v.y = S[(size_t)(4*lane+1)*ss + r];
  v.z = S[(size_t)(4*lane+2)*ss + r]; v.w = S[(size_t)(4*lane+3)*ss + r];
  ((float4*)D)[(size_t)r * nc4 + lane] = v;
}

// ---- GJ pivot loop v2: ONE sync/pivot, unscaled publish, double-buffered ----
// 64x192 augmented, 512 thr = 64 rows x 8 chunks of 24 cols.
__device__ __forceinline__ void gjcore2(float (&a)[24], float* piv2, float* fc2, float* sinv) {
  int r = threadIdx.x & 63, ch = threadIdx.x >> 6, c0 = ch * 24;
  int pc = 0, pi = 0;
#pragma unroll 1
  for (int p = 0; p < 64; p++) {
    int par = p & 1;
    float* piv = piv2 + par * 192;
    float* fc  = fc2 + par * 64;
    if (ch == pc) {
      float v = a[pi];
      fc[r] = v;                                  // unscaled multiplier column
      if (r == p) sinv[par] = 1.0f / v;           // reciprocal off the post-sync path
    }
    if (r == p) {                                 // publish unscaled pivot row chunk
#pragma unroll
      for (int j = 0; j < 24; j++) piv[c0 + j] = a[j];
    }
    __syncthreads();
    float inv = sinv[par];
    if (r == p) {                                 // scale own row lazily
#pragma unroll
      for (int j = 0; j < 24; j++) a[j] *= inv;
    } else if (c0 + 23 >= p) {                    // skip fully-dead left chunks
      float f = fc[r] * inv;
#pragma unroll
      for (int j = 0; j < 24; j++) a[j] = fmaf(-f, piv[c0 + j], a[j]);
    }
    if (++pi == 24) { pi = 0; pc++; }
  }
}

// ---- persistent serial-chain kernel ----
__global__ void __launch_bounds__(PT, 1) kchain(const float* F, const float* H, const float* Q,
                                                const float* R, const float* P0) {
  __shared__ __align__(16) float sYv[64*128];    // declared FIRST: float4-aligned
  __shared__ __align__(16) float sw[6][132];
  __shared__ __align__(16) float piv[384];
  __shared__ __align__(16) float fc[128];
  __shared__ float sinv[2];
  int wid = threadIdx.x >> 5, lane = threadIdx.x & 31;
  int gw = blockIdx.x * 16 + wid;
  const int NW = PC * 16;
  unsigned gen = dFlags[blockIdx.x * 32];
  // S0
  for (int w = gw; w < 640; w += NW) {
    if (w < 128) prow(F, F, 0, dF2, w, 128, 128, 1.f);
    else if (w < 256) prow(F, P0, 0, dA, w-128, 128, 128, 1.f);
    else if (w < 384) prow(F, Q, 0, dA+NN, w-256, 128, 128, 1.f);
    else if (w < 512) trow(F, dF1T, w-384, 128, 128);
    else trow(H, dHT, w-512, 64, 128);
  }
  gbar(++gen);
  // S1
  for (int w = gw; w < 768; w += NW) {
    if (w < 128) prow(F, dF2, 0, dF3, w, 128, 128, 1.f);
    else if (w < 256) prow(dF2, dF2, 0, dF4, w-128, 128, 128, 1.f);
    else if (w < 384) trow(dF2, dF2T, w-256, 128, 128);
    else if (w < 512) prow(dA+NN, dF1T, 0, dB+NN, w-384, 128, 128, 1.f);
    else if (w < 640) prow(dF2, Q, 0, dA+2*NN, w-512, 128, 128, 1.f);
    else prow(dA, dF1T, Q, dPp, w-640, 128, 128, 1.f);
  }
  gbar(++gen);
  // S2
  for (int w = gw; w < 896; w += NW) {
    if (w < 128) prow(dF2, dF3, 0, dF5, w, 128, 128, 1.f);
    else if (w < 256) prow(dF3, dF3, 0, dF6, w-128, 128, 128, 1.f);
    else if (w < 384) trow(dF3, dF3T, w-256, 128, 128);
    else if (w < 512) trow(dF4, dF4T, w-384, 128, 128);
    else if (w < 640) prow(dA+2*NN, dF2T, 0, dB+2*NN, w-512, 128, 128, 1.f);
    else if (w < 768) prow(dF3, Q, 0, dA+3*NN, w-640, 128, 128, 1.f);
    else prow(dF4, Q, 0, dA+4*NN, w-768, 128, 128, 1.f);
  }
  gbar(++gen);
  // S3
  for (int w = gw; w < 640; w += NW) {
    if (w < 128) trow(dF5, dF5T, w, 128, 128);
    else if (w < 256) trow(dF6, dF6T, w-128, 128, 128);
    else if (w < 384) prow(dA+3*NN, dF3T, 0, dB+3*NN, w-256, 128, 128, 1.f);
    else if (w < 512) prow(dA+4*NN, dF4T, 0, dB+4*NN, w-384, 128, 128, 1.f);
    else prow(dF5, Q, 0, dA+5*NN, w-512, 128, 128, 1.f);
  }
  gbar(++gen);
  // S4
  for (int w = gw; w < 640; w += NW) {
    if (w < 128) prow(dA+5*NN, dF5T, 0, dB+5*NN, w, 128, 128, 1.f);
    else {
      int i = (w - 128) * 32 + lane;
      float q  = Q[i];
      float q2 = q  + dB[1*NN+i]; dQ2[i] = q2;
      float q3 = q2 + dB[2*NN+i]; dQ3[i] = q3;
      float q4 = q3 + dB[3*NN+i]; dQ4[i] = q4;
      float q5 = q4 + dB[4*NN+i]; dQ5[i] = q5;
    }
  }
  gbar(++gen);
  // ---- 31 observation cycles ----
  for (int c = 0; c < Kn; c++) {
    const float4* Pc4 = (const float4*)(dPp + (size_t)c * NN);
    int task = blockIdx.x * 6 + wid;             // wid 0..5 -> 192 tasks
    if (wid < 6) {
      const float* Ar = (task < 128) ? (dF3 + (size_t)task * 128)
                                     : (H + (size_t)(task - 128) * 128);
      float4 w = make_float4(0.f, 0.f, 0.f, 0.f);
      for (int kb = 0; kb < 128; kb += 8) {
        float4 bt[8]; float at[8];
#pragma unroll
        for (int j = 0; j < 8; j++) { bt[j] = Pc4[(kb+j)*32 + lane]; at[j] = Ar[kb+j]; }
#pragma unroll
        for (int j = 0; j < 8; j++) {
          w.x = fmaf(at[j], bt[j].x, w.x); w.y = fmaf(at[j], bt[j].y, w.y);
          w.z = fmaf(at[j], bt[j].z, w.z); w.w = fmaf(at[j], bt[j].w, w.w);
        }
      }
      ((float4*)(sw[wid]))[lane] = w;
      __syncwarp();
      const float* swr = sw[wid];
      if (task < 128) {                          // G,S rows
        int row = task;
        float g0 = 0.f, g1 = 0.f;
        float4 s = make_float4(0.f, 0.f, 0.f, 0.f);
        const float4* F3T4 = (const float4*)dF3T;
        const float2* HT2 = (const float2*)dHT;
        for (int kb = 0; kb < 128; kb += 8) {
          float4 ft[8]; float2 ht[8];
#pragma unroll
          for (int j = 0; j < 8; j++) { ft[j] = F3T4[(kb+j)*32 + lane]; ht[j] = HT2[(kb+j)*32 + lane]; }
#pragma unroll
          for (int j = 0; j < 8; j++) {
            float wk = swr[kb+j];
            g0 = fmaf(wk, ht[j].x, g0); g1 = fmaf(wk, ht[j].y, g1);
            s.x = fmaf(wk, ft[j].x, s.x); s.y = fmaf(wk, ft[j].y, s.y);
            s.z = fmaf(wk, ft[j].z, s.z); s.w = fmaf(wk, ft[j].w, s.w);
          }
        }
        float4 q = ((const float4*)(dQ3 + (size_t)row * 128))[lane];
        s.x += q.x; s.y += q.y; s.z += q.z; s.w += q.w;
        ((float4*)(dS + (size_t)c*NN + (size_t)row*128))[lane] = s;
        ((float2*)(dG + (size_t)c*MN + (size_t)row*64))[lane] = make_float2(g0, g1);
      } else {                                   // U,Py rows
        int row = task - 128;
        ((float4*)(dU + (size_t)c*MN + (size_t)row*128))[lane] = w;
        float p0 = 0.f, p1 = 0.f;
        const float2* HT2 = (const float2*)dHT;
        for (int kb = 0; kb < 128; kb += 8) {
          float2 ht[8];
#pragma unroll
          for (int j = 0; j < 8; j++) ht[j] = HT2[(kb+j)*32 + lane];
#pragma unroll
          for (int j = 0; j < 8; j++) {
            float wk = swr[kb+j];
            p0 = fmaf(wk, ht[j].x, p0); p1 = fmaf(wk, ht[j].y, p1);
          }
        }
        p0 += R[row*64 + 2*lane]; p1 += R[row*64 + 2*lane + 1];
        ((float2*)(dPy + (size_t)c*MM + (size_t)row*64))[lane] = make_float2(p0, p1);
      }
    }
    gbar(++gen);
    // GJ redundantly in every CTA: sYv = Py^-1 @ G^T
    {
      int r = threadIdx.x & 63, ch = threadIdx.x >> 6, c0 = ch * 24;
      const float* Pyc = dPy + (size_t)c * MM;
      const float* Gc  = dG + (size_t)c * MN;
      float a[24];
#pragma unroll
      for (int j = 0; j < 24; j++) {
        int col = c0 + j;
        a[j] = (col < 64) ? Pyc[r*64 + col] : Gc[(size_t)(col-64)*64 + r];
      }
      gjcore2(a, piv, fc, sinv);
#pragma unroll
      for (int j = 0; j < 24; j++) {
        int col = c0 + j;
        if (col >= 64) sYv[r*128 + (col-64)] = a[j];
      }
      __syncthreads();
    }
    // Pp' = S - G @ sYv  (4 rows per CTA, one per warp)
    if (wid < 4) {
      int row = blockIdx.x * 4 + wid;
      const float* Gr = dG + (size_t)c*MN + (size_t)row*64;
      float4 acc = ((const float4*)(dS + (size_t)c*NN + (size_t)row*128))[lane];
      for (int ab = 0; ab < 64; ab += 8) {
        float gt[8];
#pragma unroll
        for (int j = 0; j < 8; j++) gt[j] = Gr[ab+j];
#pragma unroll
        for (int j = 0; j < 8; j++) {
          float4 yv = ((const float4*)(sYv + (ab+j)*128))[lane];
          acc.x = fmaf(-gt[j], yv.x, acc.x); acc.y = fmaf(-gt[j], yv.y, acc.y);
          acc.z = fmaf(-gt[j], yv.z, acc.z); acc.w = fmaf(-gt[j], yv.w, acc.w);
        }
      }
      ((float4*)(dPp + (size_t)(c+1)*NN + (size_t)row*128))[lane] = acc;
    }
    gbar(++gen);
  }
}

// ---- post kernels ----
__global__ void __launch_bounds__(512, 1) kgjpost() {   // Z_c = Py_c^-1 @ U_c
  __shared__ __align__(16) float piv[384];
  __shared__ __align__(16) float fc[128];
  __shared__ float sinv[2];
  int c = blockIdx.x;
  int r = threadIdx.x & 63, ch = threadIdx.x >> 6, c0 = ch * 24;
  float a[24];
#pragma unroll
  for (int j = 0; j < 24; j++) {
    int col = c0 + j;
    a[j] = (col < 64) ? dPy[(size_t)c*MM + r*64 + col]
                      : dU[(size_t)c*MN + r*128 + (col-64)];
  }
  gjcore2(a, piv, fc, sinv);
#pragma unroll
  for (int j = 0; j < 24; j++) {
    int col = c0 + j;
    if (col >= 64) dZ[(size_t)c*MN + r*128 + (col-64)] = a[j];
  }
}
__global__ void __launch_bounds__(256, 1) kPu() {       // Pu = Pp - U^T @ Z
  int c = blockIdx.y, w = blockIdx.x * 8 + (threadIdx.x >> 5), lane = threadIdx.x & 31;
  const float* U = dU + (size_t)c*MN;
  const float4* Z4 = (const float4*)(dZ + (size_t)c*MN);
  float4 acc = ((const float4*)(dPp + (size_t)c*NN))[w*32 + lane];
  for (int ab = 0; ab < 64; ab += 8) {
    float gt[8]; float4 zt[8];
#pragma unroll
    for (int j = 0; j < 8; j++) { gt[j] = U[(ab+j)*128 + w]; zt[j] = Z4[(ab+j)*32 + lane]; }
#pragma unroll
    for (int j = 0; j < 8; j++) {
      acc.x = fmaf(-gt[j], zt[j].x, acc.x); acc.y = fmaf(-gt[j], zt[j].y, acc.y);
      acc.z = fmaf(-gt[j], zt[j].z, acc.z); acc.w = fmaf(-gt[j], zt[j].w, acc.w);
    }
  }
  ((float4*)(dPt + (size_t)(4*c)*NN))[w*32 + lane] = acc;
}
// fused: P[4c+2] = F Pu F1T + Q ; P[4c+3] = F2 Pu F2T + Q2
__global__ void __launch_bounds__(256, 1) kPmid(const float* F, const float* Q) {
  __shared__ __align__(16) float sw[8][132];
  int wid = threadIdx.x >> 5, lane = threadIdx.x & 31;
  int c = blockIdx.y;
  int tk = blockIdx.x * 8 + wid;
  int jj = tk >> 7, row = tk & 127;
  const float* A  = jj ? dF2 : F;
  const float4* Bt4 = (const float4*)(jj ? dF2T : dF1T);
  const float4* Qj4 = (const float4*)((jj ? dQ2 : Q) + (size_t)row*128);
  const float4* Pu4 = (const float4*)(dPt + (size_t)(4*c)*NN);
  const float* Ar = A + (size_t)row*128;
  float4 w = make_float4(0.f,0.f,0.f,0.f);
  for (int kb = 0; kb < 128; kb += 8) {
    float4 bt[8]; float at[8];
#pragma unroll
    for (int j = 0; j < 8; j++) { bt[j] = Pu4[(kb+j)*32 + lane]; at[j] = Ar[kb+j]; }
#pragma unroll
    for (int j = 0; j < 8; j++) {
      w.x = fmaf(at[j], bt[j].x, w.x); w.y = fmaf(at[j], bt[j].y, w.y);
      w.z = fmaf(at[j], bt[j].z, w.z); w.w = fmaf(at[j], bt[j].w, w.w);
    }
  }
  ((float4*)(sw[wid]))[lane] = w;
  __syncwarp();
  const float* swr = sw[wid];
  float4 o = Qj4[lane];
  for (int kb = 0; kb < 128; kb += 8) {
    float4 ft[8];
#pragma unroll
    for (int j = 0; j < 8; j++) ft[j] = Bt4[(kb+j)*32 + lane];
#pragma unroll
    for (int j = 0; j < 8; j++) {
      float wk = swr[kb+j];
      o.x = fmaf(wk, ft[j].x, o.x); o.y = fmaf(wk, ft[j].y, o.y);
      o.z = fmaf(wk, ft[j].z, o.z); o.w = fmaf(wk, ft[j].w, o.w);
    }
  }
  ((float4*)(dPt + (size_t)(4*c + 2 + jj)*NN + (size_t)row*128))[lane] = o;
}
// fused tail: P[125+k] = F^{4+k} Pu30 F^{4+k}T + Q_{4+k}
__global__ void __launch_bounds__(256, 1) kPtail(const float* Q) {
  __shared__ __align__(16) float sw[8][132];
  int wid = threadIdx.x >> 5, lane = threadIdx.x & 31;
  int k = blockIdx.y;
  int row = blockIdx.x * 8 + wid;
  const float* A  = (k == 0) ? dF4 : (k == 1) ? dF5 : dF6;
  const float4* Bt4 = (const float4*)((k == 0) ? dF4T : (k == 1) ? dF5T : dF6T);
  const float4* Qk4 = (const float4*)(((k == 0) ? dQ4 : dQ5) + (size_t)row*128);
  const float4* Pu4 = (const float4*)(dPt + (size_t)120*NN);
  const float* Ar = A + (size_t)row*128;
  float4 w = make_float4(0.f,0.f,0.f,0.f);
  for (int kb = 0; kb < 128; kb += 8) {
    float4 bt[8]; float at[8];
#pragma unroll
    for (int j = 0; j < 8; j++) { bt[j] = Pu4[(kb+j)*32 + lane]; at[j] = Ar[kb+j]; }
#pragma unroll
    for (int j = 0; j < 8; j++) {
      w.x = fmaf(at[j], bt[j].x, w.x); w.y = fmaf(at[j], bt[j].y, w.y);
      w.z = fmaf(at[j], bt[j].z, w.z); w.w = fmaf(at[j], bt[j].w, w.w);
    }
  }
  ((float4*)(sw[wid]))[lane] = w;
  __syncwarp();
  const float* swr = sw[wid];
  float4 o = Qk4[lane];
  if (k == 2) {
    float4 b5 = ((const float4*)(dB + 5*NN + (size_t)row*128))[lane];
    o.x += b5.x; o.y += b5.y; o.z += b5.z; o.w += b5.w;
  }
  for (int kb = 0; kb < 128; kb += 8) {
    float4 ft[8];
#pragma unroll
    for (int j = 0; j < 8; j++) ft[j] = Bt4[(kb+j)*32 + lane];
#pragma unroll
    for (int j = 0; j < 8; j++) {
      float wk = swr[kb+j];
      o.x = fmaf(wk, ft[j].x, o.x); o.y = fmaf(wk, ft[j].y, o.y);
      o.z = fmaf(wk, ft[j].z, o.z); o.w = fmaf(wk, ft[j].w, o.w);
    }
  }
  ((float4*)(dPt + (size_t)(125 + k)*NN + (size_t)row*128))[lane] = o;
}
__global__ void __launch_bounds__(256, 1) kcopy() {
  int i = blockIdx.x * 256 + threadIdx.x;
  ((float4*)(dPt + (size_t)124*NN))[i] = ((const float4*)(dPp + (size_t)Kn*NN))[i];
}

// ---- per-batch state trajectory: F row in registers, HT in smem ----
__global__ void __launch_bounds__(128, 1) xphase(const float* __restrict__ x0,
                                                 const float* __restrict__ y,
                                                 const float* __restrict__ Fg,
                                                 float* __restrict__ xs) {
  __shared__ float sx[128], sxp[128], sres[64];
  __shared__ float sHT[128*65];
  int b = blockIdx.x, i = threadIdx.x;
  float fr[128];
#pragma unroll
  for (int j = 0; j < 128; j++) fr[j] = Fg[i*128 + j];
  for (int idx = i; idx < 128*64; idx += 128) {
    int j = idx >> 6, a = idx & 63;
    sHT[j*65 + a] = dHT[idx];
  }
  sx[i] = x0[b*128 + i];
  __syncthreads();
#pragma unroll 1
  for (int t = 0; t < 128; t++) {
    bool isobs = ((t & 3) == 0) && (t <= 120);
    bool copys = (t >= 1) && (((t-1) & 3) == 0) && ((t-1) <= 120);
    float xp;
    if (!copys) {
      float a0 = 0.f, a1 = 0.f;
#pragma unroll
      for (int j = 0; j < 128; j += 2) {
        a0 = fmaf(fr[j], sx[j], a0);
        a1 = fmaf(fr[j+1], sx[j+1], a1);
      }
      xp = a0 + a1;
    } else xp = sx[i];
    __syncthreads();
    sxp[i] = xp;
    __syncthreads();
    float xn = xp;
    if (isobs) {
      int c = t >> 2;
      if (i < 64) {
        float acc = 0.f;
#pragma unroll
        for (int j = 0; j < 128; j++) acc = fmaf(sHT[j*65 + i], sxp[j], acc);
        sres[i] = y[((size_t)b*Kn + c)*64 + i] - acc;
      }
      __syncthreads();
      const float* Zc = dZ + (size_t)c*MN;
      float acc = 0.f;
      for (int ab = 0; ab < 64; ab += 8) {
        float zt[8];
#pragma unroll
        for (int j = 0; j < 8; j++) zt[j] = Zc[(ab+j)*128 + i];
#pragma unroll
        for (int j = 0; j < 8; j++) acc = fmaf(zt[j], sres[ab+j], acc);
      }
      xn = xp + acc;
    }
    xs[((size_t)b*128 + t)*128 + i] = xn;
    __syncthreads();
    sx[i] = xn;
    __syncthreads();
  }
}
__global__ void __launch_bounds__(256, 1) kbcast(float4* __restrict__ Ps) {
  int idx = blockIdx.x * blockDim.x + threadIdx.x;
  int b = blockIdx.y;
  int t = idx >> 12;
  int ts = (((t & 3) == 1) && (t < 122)) ? (t - 1) : t;
  Ps[(size_t)b * 524288 + idx] = ((const float4*)dPt)[(size_t)ts * 4096 + (idx & 4095)];
}

extern "C" void kernel_launch(void* const* d_in, const int* in_sizes, int n_in,
                              void* d_out, int out_size) {
  (void)in_sizes; (void)n_in; (void)out_size;
  const float* y  = (const float*)d_in[1];
  const float* x0 = (const float*)d_in[2];
  const float* P0 = (const float*)d_in[3];
  const float* F  = (const float*)d_in[5];
  const float* H  = (const float*)d_in[6];
  const float* Q  = (const float*)d_in[7];
  const float* R  = (const float*)d_in[8];
  float* xs = (float*)d_out;
  float* Ps = (float*)d_out + (size_t)32 * 128 * 128;

  kchain<<<PC, PT>>>(F, H, Q, R, P0);
  kgjpost<<<Kn, 512>>>();
  kPu<<<dim3(16, Kn), 256>>>();
  kPmid<<<dim3(32, Kn), 256>>>(F, Q);
  kPtail<<<dim3(16, 3), 256>>>(Q);
  kcopy<<<16, 256>>>();
  xphase<<<32, 128>>>(x0, y, F, xs);
  kbcast<<<dim3(2048, 32), 256>>>((float4*)Ps);
}